// round 1
// baseline (speedup 1.0000x reference)
#include <cuda_runtime.h>
#include <math.h>

#define BB 16
#define NN 64
#define TT 50
#define DD 4
#define NEMB 128
#define EPS 1e-20f

__device__ __forceinline__ float selu_f(float v) {
    const float scale = 1.0507009873554805f;
    const float alpha = 1.6732632423543772f;
    return v > 0.f ? scale * v : scale * alpha * expm1f(v);
}

__global__ __launch_bounds__(256, 6)
void gcn_fused_kernel(const float* __restrict__ x,
                      const float* __restrict__ Wc,
                      const float* __restrict__ bc,
                      const float* __restrict__ Ws,
                      const float* __restrict__ bs,
                      float* __restrict__ out)
{
    const int bt  = blockIdx.x;          // 0..B*T-1
    const int b   = bt / TT;
    const int t   = bt % TT;
    const int tid = threadIdx.x;

    __shared__ float4 sx[NN];            // x[b, :, t, :]       (1 KB)
    __shared__ float4 sxd[NN];           // dinv[m] * x[m]      (1 KB)
    __shared__ float4 sy[NN];            // (A_n @ x)[n]        (1 KB)
    __shared__ float  w[NN][NN + 1];     // pairwise weights, padded (16.6 KB)
    __shared__ float  dinv[NN];
    __shared__ float4 sWc[NEMB];         // W_conv column c as float4 over D
    __shared__ float4 sWs[NEMB];         // W_skip column c
    __shared__ float  sbc[NEMB];
    __shared__ float  sbs[NEMB];

    // ---- load x tile (float4 per node) and weights ----
    if (tid < NN) {
        const float4* p = reinterpret_cast<const float4*>(
            x + ((size_t)(b * NN + tid) * TT + t) * DD);
        sx[tid] = *p;
    }
    if (tid < NEMB) {
        sWc[tid] = make_float4(Wc[0 * NEMB + tid], Wc[1 * NEMB + tid],
                               Wc[2 * NEMB + tid], Wc[3 * NEMB + tid]);
        sbc[tid] = bc[tid];
    } else {
        const int c = tid - NEMB;
        sWs[c] = make_float4(Ws[0 * NEMB + c], Ws[1 * NEMB + c],
                             Ws[2 * NEMB + c], Ws[3 * NEMB + c]);
        sbs[c] = bs[c];
    }
    __syncthreads();

    // ---- pairwise inverse distances: 4096 entries, 16 per thread ----
    #pragma unroll
    for (int k = 0; k < 16; k++) {
        const int e = tid + k * 256;
        const int s = e >> 6;
        const int r = e & 63;
        const float4 a = sx[s];
        const float4 c = sx[r];
        const float d0 = a.x - c.x, d1 = a.y - c.y, d2 = a.z - c.z, d3 = a.w - c.w;
        const float dist = sqrtf(d0 * d0 + d1 * d1 + d2 * d2 + d3 * d3);
        w[s][r] = (s == r) ? 0.f : 1.f / (dist + EPS);
    }
    __syncthreads();

    // ---- degree + D^{-1/2} ----
    if (tid < NN) {
        float deg = 0.f;
        #pragma unroll
        for (int m = 0; m < NN; m++) deg += w[tid][m];
        const float di = rsqrtf(deg + EPS);
        dinv[tid] = di;
        const float4 v = sx[tid];
        sxd[tid] = make_float4(v.x * di, v.y * di, v.z * di, v.w * di);
    }
    __syncthreads();

    // ---- y[n] = dinv[n] * sum_m w[n][m] * (dinv[m] * x[m])  -> [64,4] ----
    if (tid < NN) {
        float4 acc = make_float4(0.f, 0.f, 0.f, 0.f);
        #pragma unroll
        for (int m = 0; m < NN; m++) {
            const float wm = w[tid][m];
            const float4 v = sxd[m];
            acc.x += wm * v.x; acc.y += wm * v.y;
            acc.z += wm * v.z; acc.w += wm * v.w;
        }
        const float di = dinv[tid];
        sy[tid] = make_float4(acc.x * di, acc.y * di, acc.z * di, acc.w * di);
    }
    __syncthreads();

    // ---- output: 64 nodes x 256 channels, float4 stores ----
    // 16 iterations, 4 node-rows per iteration, 64 threads (64 float4) per row.
    const int rowq = tid >> 6;           // 0..3  : which of the 4 rows this iter
    const int cg   = tid & 63;           // 0..63 : float4 group within the row
    const int cc   = cg * 4;             // starting channel (0..252)
    const bool is_skip = (cc < NEMB);
    const int  ch      = is_skip ? cc : (cc - NEMB);
    const float4 w0 = is_skip ? sWs[ch + 0] : sWc[ch + 0];
    const float4 w1 = is_skip ? sWs[ch + 1] : sWc[ch + 1];
    const float4 w2 = is_skip ? sWs[ch + 2] : sWc[ch + 2];
    const float4 w3 = is_skip ? sWs[ch + 3] : sWc[ch + 3];
    const float  bi0 = is_skip ? sbs[ch + 0] : sbc[ch + 0];
    const float  bi1 = is_skip ? sbs[ch + 1] : sbc[ch + 1];
    const float  bi2 = is_skip ? sbs[ch + 2] : sbc[ch + 2];
    const float  bi3 = is_skip ? sbs[ch + 3] : sbc[ch + 3];

    #pragma unroll
    for (int it = 0; it < 16; it++) {
        const int n = it * 4 + rowq;
        const float4 v = is_skip ? sx[n] : sy[n];
        float4 o;
        o.x = selu_f(v.x * w0.x + v.y * w0.y + v.z * w0.z + v.w * w0.w + bi0);
        o.y = selu_f(v.x * w1.x + v.y * w1.y + v.z * w1.z + v.w * w1.w + bi1);
        o.z = selu_f(v.x * w2.x + v.y * w2.y + v.z * w2.z + v.w * w2.w + bi2);
        o.w = selu_f(v.x * w3.x + v.y * w3.y + v.z * w3.z + v.w * w3.w + bi3);
        float4* op = reinterpret_cast<float4*>(
            out + (((size_t)(b * NN + n) * TT + t) * 2 * NEMB + cc));
        *op = o;
    }
}

extern "C" void kernel_launch(void* const* d_in, const int* in_sizes, int n_in,
                              void* d_out, int out_size)
{
    // metadata order: x, rel_rec, rel_send, W_conv, b_conv, W_skip, b_skip
    const float* x  = (const float*)d_in[0];
    const float* Wc = (const float*)d_in[3];
    const float* bc = (const float*)d_in[4];
    const float* Ws = (const float*)d_in[5];
    const float* bs = (const float*)d_in[6];
    float* out = (float*)d_out;

    gcn_fused_kernel<<<BB * TT, 256>>>(x, Wc, bc, Ws, bs, out);
}

// round 2
// speedup vs baseline: 1.9678x; 1.9678x over previous
#include <cuda_runtime.h>
#include <math.h>

#define BB 16
#define NN 64
#define TT 50
#define DD 4
#define NEMB 128
#define EPS 1e-20f

__device__ __forceinline__ float selu_f(float v) {
    const float scale  = 1.0507009873554805f;
    const float salpha = 1.7580993408473766f;   // scale * alpha
    float e   = __expf(v);                       // MUFU.EX2 path
    float neg = salpha * e - salpha;             // scale*alpha*(e^v - 1)
    float pos = scale * v;
    return v > 0.f ? pos : neg;
}

__global__ __launch_bounds__(256, 6)
void gcn_fused_kernel(const float* __restrict__ x,
                      const float* __restrict__ Wc,
                      const float* __restrict__ bc,
                      const float* __restrict__ Ws,
                      const float* __restrict__ bs,
                      float* __restrict__ out)
{
    const int bt  = blockIdx.x;          // 0..B*T-1
    const int b   = bt / TT;
    const int t   = bt % TT;
    const int tid = threadIdx.x;

    __shared__ float4 sx[NN];            // x[b, :, t, :]                 1 KB
    __shared__ float4 sxd[NN];           // dinv[m] * x[m]                1 KB
    __shared__ float4 sy[NN];            // normalized conv input         1 KB
    __shared__ float  w[NN][NN + 1];     // pairwise weights, padded     16.6 KB
    __shared__ float  pdeg[4 * NN];      // partial degree sums           1 KB
    __shared__ float4 psum[4 * NN];      // partial y sums                4 KB
    __shared__ float  dinv[NN];
    __shared__ float4 sWc[NEMB];         // W_conv column as float4 over D
    __shared__ float4 sWs[NEMB];
    __shared__ float  sbc[NEMB];
    __shared__ float  sbs[NEMB];

    // ---- load x tile and weights ----
    if (tid < NN) {
        const float4* p = reinterpret_cast<const float4*>(
            x + ((size_t)(b * NN + tid) * TT + t) * DD);
        sx[tid] = *p;
    }
    if (tid < NEMB) {
        sWc[tid] = make_float4(Wc[0 * NEMB + tid], Wc[1 * NEMB + tid],
                               Wc[2 * NEMB + tid], Wc[3 * NEMB + tid]);
        sbc[tid] = bc[tid];
    } else {
        const int c = tid - NEMB;
        sWs[c] = make_float4(Ws[0 * NEMB + c], Ws[1 * NEMB + c],
                             Ws[2 * NEMB + c], Ws[3 * NEMB + c]);
        sbs[c] = bs[c];
    }
    __syncthreads();

    // ---- pairwise inverse distances + fused partial degree ----
    // thread (r = tid&63, q = tid>>6) handles w[r][16q .. 16q+15]
    const int r = tid & 63;
    const int q = tid >> 6;
    {
        const float4 a = sx[r];
        float degp = 0.f;
        #pragma unroll
        for (int k = 0; k < 16; k++) {
            const int m = q * 16 + k;
            const float4 c = sx[m];            // broadcast within warp
            const float d0 = a.x - c.x, d1 = a.y - c.y;
            const float d2_ = a.z - c.z, d3 = a.w - c.w;
            const float dd = d0 * d0 + d1 * d1 + d2_ * d2_ + d3 * d3;
            const float wv = (m == r) ? 0.f : rsqrtf(dd);   // 1/(||.||+1e-20) ~ rsqrt
            w[r][m] = wv;                      // stride-65: conflict-free
            degp += wv;
        }
        pdeg[q * NN + r] = degp;
    }
    __syncthreads();

    // ---- dinv + pre-scaled x ----
    if (tid < NN) {
        const float deg = pdeg[tid] + pdeg[NN + tid] + pdeg[2 * NN + tid] + pdeg[3 * NN + tid];
        const float di  = rsqrtf(deg + EPS);
        dinv[tid] = di;
        const float4 v = sx[tid];
        sxd[tid] = make_float4(v.x * di, v.y * di, v.z * di, v.w * di);
    }
    __syncthreads();

    // ---- y[r] = dinv[r] * sum_m w[r][m] * sxd[m]  (partial over m-chunk) ----
    {
        float4 acc = make_float4(0.f, 0.f, 0.f, 0.f);
        #pragma unroll
        for (int k = 0; k < 16; k++) {
            const int m = q * 16 + k;
            const float wv = w[r][m];
            const float4 v = sxd[m];           // broadcast
            acc.x += wv * v.x; acc.y += wv * v.y;
            acc.z += wv * v.z; acc.w += wv * v.w;
        }
        psum[q * NN + r] = acc;
    }
    __syncthreads();

    if (tid < NN) {
        const float4 a0 = psum[tid];
        const float4 a1 = psum[NN + tid];
        const float4 a2 = psum[2 * NN + tid];
        const float4 a3 = psum[3 * NN + tid];
        const float di = dinv[tid];
        sy[tid] = make_float4((a0.x + a1.x + a2.x + a3.x) * di,
                              (a0.y + a1.y + a2.y + a3.y) * di,
                              (a0.z + a1.z + a2.z + a3.z) * di,
                              (a0.w + a1.w + a2.w + a3.w) * di);
    }
    __syncthreads();

    // ---- output: 64 nodes x 256 channels, float4 stores ----
    const int rowq = tid >> 6;           // which of 4 rows per iteration
    const int cg   = tid & 63;           // float4 group within the row
    const int cc   = cg * 4;             // starting channel
    const bool is_skip = (cc < NEMB);
    const int  ch      = is_skip ? cc : (cc - NEMB);
    const float4 w0 = is_skip ? sWs[ch + 0] : sWc[ch + 0];
    const float4 w1 = is_skip ? sWs[ch + 1] : sWc[ch + 1];
    const float4 w2 = is_skip ? sWs[ch + 2] : sWc[ch + 2];
    const float4 w3 = is_skip ? sWs[ch + 3] : sWc[ch + 3];
    const float  bi0 = is_skip ? sbs[ch + 0] : sbc[ch + 0];
    const float  bi1 = is_skip ? sbs[ch + 1] : sbc[ch + 1];
    const float  bi2 = is_skip ? sbs[ch + 2] : sbc[ch + 2];
    const float  bi3 = is_skip ? sbs[ch + 3] : sbc[ch + 3];

    #pragma unroll
    for (int it = 0; it < 16; it++) {
        const int n = it * 4 + rowq;
        const float4 v = is_skip ? sx[n] : sy[n];
        float4 o;
        o.x = selu_f(v.x * w0.x + v.y * w0.y + v.z * w0.z + v.w * w0.w + bi0);
        o.y = selu_f(v.x * w1.x + v.y * w1.y + v.z * w1.z + v.w * w1.w + bi1);
        o.z = selu_f(v.x * w2.x + v.y * w2.y + v.z * w2.z + v.w * w2.w + bi2);
        o.w = selu_f(v.x * w3.x + v.y * w3.y + v.z * w3.z + v.w * w3.w + bi3);
        float4* op = reinterpret_cast<float4*>(
            out + (((size_t)(b * NN + n) * TT + t) * 2 * NEMB + cc));
        *op = o;
    }
}

extern "C" void kernel_launch(void* const* d_in, const int* in_sizes, int n_in,
                              void* d_out, int out_size)
{
    // metadata order: x, rel_rec, rel_send, W_conv, b_conv, W_skip, b_skip
    const float* x  = (const float*)d_in[0];
    const float* Wc = (const float*)d_in[3];
    const float* bc = (const float*)d_in[4];
    const float* Ws = (const float*)d_in[5];
    const float* bs = (const float*)d_in[6];
    float* out = (float*)d_out;

    gcn_fused_kernel<<<BB * TT, 256>>>(x, Wc, bc, Ws, bs, out);
}